// round 15
// baseline (speedup 1.0000x reference)
#include <cuda_runtime.h>
#include <math.h>

#define NMAX 100000
#define EMAX 1600000
#define SCAN_B 1024
#define NBLK ((NMAX + SCAN_B - 1) / SCAN_B)   // 98

// Scratch (__device__ globals; no allocation allowed)
__device__ int      g_cnt[NMAX];           // zero-initialized; re-zeroed by scan_local
__device__ float    g_dinv[NMAX];
__device__ int      g_rowstart[NMAX + 1];
__device__ int      g_fill[NMAX];
__device__ int      g_bsum[NBLK + 1];
__device__ int      g_csr[EMAX];           // src index only (norm factorized out)
__device__ float    g_tmp[NMAX * 64];      // aggregation output (fp32, pre-GEMM)
__device__ unsigned g_x16[NMAX * 32];      // pre-scaled input features as bf16x2
__device__ unsigned g_a[NMAX * 32];        // activations as bf16x2 (ping)
__device__ unsigned g_b[NMAX * 32];        // activations as bf16x2 (pong)

// bf16 pack/unpack: unpack is ALU-pipe only (SHF/LOP3), no F2F.
#define PACK_BF16X2(r, lo, hi) \
    asm("cvt.rn.bf16x2.f32 %0, %1, %2;" : "=r"(r) : "f"(hi), "f"(lo))
__device__ __forceinline__ float bf_lo(unsigned u) { return __uint_as_float(u << 16); }
__device__ __forceinline__ float bf_hi(unsigned u) { return __uint_as_float(u & 0xffff0000u); }

// ---------------------------------------------------------------------------
__global__ void count_kernel(const int* __restrict__ dst, int E) {
    int i = blockIdx.x * blockDim.x + threadIdx.x;
    if (i < E) atomicAdd(&g_cnt[dst[i]], 1);
}

// ---------------------------------------------------------------------------
// scan_local: per-block scan of g_cnt, block totals to g_bsum.
// Also computes dinv and RE-ZEROES g_cnt for the next replay.
// ---------------------------------------------------------------------------
__global__ void scan_local_kernel(int n) {
    __shared__ int sm[SCAN_B];
    int t = threadIdx.x;
    int i = blockIdx.x * SCAN_B + t;
    int v = (i < n) ? g_cnt[i] : 0;
    if (i < n) {
        g_dinv[i] = rsqrtf((float)v + 1.0f);   // +1 self loop
        g_cnt[i] = 0;                          // ready for next replay
    }
    sm[t] = v;
    __syncthreads();
    #pragma unroll
    for (int off = 1; off < SCAN_B; off <<= 1) {
        int u = (t >= off) ? sm[t - off] : 0;
        __syncthreads();
        sm[t] += u;
        __syncthreads();
    }
    if (i < n) g_rowstart[i] = sm[t] - v;
    if (t == SCAN_B - 1) g_bsum[blockIdx.x] = sm[t];
}

// ---------------------------------------------------------------------------
// scan_apply: every block redundantly scans the 98 block sums in smem
// (cheap), then applies its offset. Eliminates the separate bsums kernel.
// ---------------------------------------------------------------------------
__global__ void scan_apply_kernel(int n, int E, int nbsum) {
    __shared__ int sm[128];
    int t = threadIdx.x;
    if (t < 128) sm[t] = (t < nbsum) ? g_bsum[t] : 0;
    __syncthreads();
    #pragma unroll
    for (int off = 1; off < 128; off <<= 1) {
        int u = (t < 128 && t >= off) ? sm[t - off] : 0;
        __syncthreads();
        if (t < 128) sm[t] += u;
        __syncthreads();
    }
    int blkoff = (blockIdx.x == 0) ? 0 : sm[blockIdx.x - 1];  // exclusive
    int i = blockIdx.x * SCAN_B + t;
    if (i < n) {
        int r = g_rowstart[i] + blkoff;
        g_rowstart[i] = r;
        g_fill[i] = r;
    }
    if (i == 0) g_rowstart[n] = E;
}

// ---------------------------------------------------------------------------
// Fused fill + input conversion (block-range split).
// fill:  csr[pos] = src  (4 B, no dinv loads — norm factorized out)
// cvt:   g_x16 = bf16x2( dinv[node] * x )   (pre-scaled features)
// ---------------------------------------------------------------------------
__global__ void fill_cvt_kernel(const int* __restrict__ src,
                                const int* __restrict__ dst,
                                const float* __restrict__ x,
                                int E, int fillBlocks, int total4) {
    int b = blockIdx.x;
    int t = threadIdx.x;
    if (b < fillBlocks) {
        int e = b * 256 + t;
        if (e < E) {
            int d = dst[e];
            int pos = atomicAdd(&g_fill[d], 1);
            g_csr[pos] = src[e];
        }
    } else {
        int i = (b - fillBlocks) * 256 + t;
        if (i < total4) {
            float4 v = ((const float4*)x)[i];
            float sc = g_dinv[i >> 4];          // 4 consecutive elems, same node
            unsigned r0, r1;
            PACK_BF16X2(r0, sc * v.x, sc * v.y);
            PACK_BF16X2(r1, sc * v.z, sc * v.w);
            ((uint2*)g_x16)[i] = make_uint2(r0, r1);
        }
    }
}

// ---------------------------------------------------------------------------
// Aggregation with factorized norm:
//   agg[d] = dinv_d * ( xs[d] + sum_j xs[src_j] )     (xs pre-scaled by dinv)
// One warp per node; lane owns feature pair (2l,2l+1) as one bf16x2 word
// (128 B row/warp). csr entries are 4 B; inner op = 2 FADDs per edge.
// ---------------------------------------------------------------------------
__global__ void agg_kernel(const unsigned* __restrict__ X, int n)
{
    int tid = threadIdx.x;
    int warp = tid >> 5, lane = tid & 31;
    int node = blockIdx.x * 8 + warp;
    if (node >= n) return;

    unsigned sx = X[(size_t)node * 32 + lane];
    float ax = bf_lo(sx);
    float ay = bf_hi(sx);

    int beg = g_rowstart[node], end = g_rowstart[node + 1];
    int j = beg;
    for (; j + 3 < end; j += 4) {
        int s0 = g_csr[j];
        int s1 = g_csr[j + 1];
        int s2 = g_csr[j + 2];
        int s3 = g_csr[j + 3];
        unsigned v0 = X[(size_t)s0 * 32 + lane];
        unsigned v1 = X[(size_t)s1 * 32 + lane];
        unsigned v2 = X[(size_t)s2 * 32 + lane];
        unsigned v3 = X[(size_t)s3 * 32 + lane];
        ax += bf_lo(v0); ay += bf_hi(v0);
        ax += bf_lo(v1); ay += bf_hi(v1);
        ax += bf_lo(v2); ay += bf_hi(v2);
        ax += bf_lo(v3); ay += bf_hi(v3);
    }
    for (; j < end; j++) {
        unsigned v = X[(size_t)g_csr[j] * 32 + lane];
        ax += bf_lo(v);
        ay += bf_hi(v);
    }

    float dd = g_dinv[node];
    ((float2*)g_tmp)[(size_t)node * 32 + lane] = make_float2(dd * ax, dd * ay);
}

// ---------------------------------------------------------------------------
// Tiled GEMM: Y(bf16x2) = [dinv *] relu(g_tmp(fp32) @ W + b).
// do_scale=1 for layers feeding another agg (output pre-scaled = xs),
// do_scale=0 for the last layer (head wants plain activations).
// Block: 256 thr, tile 128 nodes x 64. Thread tile 4x8, f32x2 packed FMAs.
// ---------------------------------------------------------------------------
#define PACKF2(out, lo, hi) \
    asm("mov.b64 %0, {%1, %2};" : "=l"(out) : "r"(__float_as_uint(lo)), "r"(__float_as_uint(hi)))
#define UNPACKF2(lo, hi, in) \
    do { unsigned _ulo, _uhi; \
         asm("mov.b64 {%0, %1}, %2;" : "=r"(_ulo), "=r"(_uhi) : "l"(in)); \
         lo = __uint_as_float(_ulo); hi = __uint_as_float(_uhi); } while (0)
#define FMA2(acc, a, b) \
    asm("fma.rn.f32x2 %0, %1, %2, %0;" : "+l"(acc) : "l"(a), "l"(b))

__global__ void gemm_kernel(unsigned* __restrict__ Y,
                            const float* __restrict__ W,
                            const float* __restrict__ bias,
                            int do_scale, int n)
{
    __shared__ float As[128 * 64];   // 32 KB
    __shared__ float Ws[64 * 64];    // 16 KB

    int tid = threadIdx.x;
    #pragma unroll
    for (int i = tid; i < 4096; i += 256) Ws[i] = W[i];

    int nb0 = blockIdx.x * 128;
    {
        int arow = tid >> 1;
        int half = tid & 1;
        float4* dstp = (float4*)(As + arow * 64) + half * 8;
        if (nb0 + arow < n) {
            const float4* srcp = (const float4*)(g_tmp + (size_t)(nb0 + arow) * 64) + half * 8;
            #pragma unroll
            for (int q = 0; q < 8; q++) dstp[q] = srcp[q];
        } else {
            float4 z = make_float4(0.f, 0.f, 0.f, 0.f);
            #pragma unroll
            for (int q = 0; q < 8; q++) dstp[q] = z;
        }
    }
    __syncthreads();

    int tc = tid & 7;
    int tr = tid >> 3;
    int c0 = tc * 8;

    unsigned long long acc[4][4];
    {
        float4 bA = *(const float4*)(bias + c0);
        float4 bB = *(const float4*)(bias + c0 + 4);
        unsigned long long b0, b1, b2, b3;
        PACKF2(b0, bA.x, bA.y); PACKF2(b1, bA.z, bA.w);
        PACKF2(b2, bB.x, bB.y); PACKF2(b3, bB.z, bB.w);
        #pragma unroll
        for (int i = 0; i < 4; i++) {
            acc[i][0] = b0; acc[i][1] = b1; acc[i][2] = b2; acc[i][3] = b3;
        }
    }

    #pragma unroll 4
    for (int k = 0; k < 64; k++) {
        float4 wA = *(const float4*)(Ws + k * 64 + c0);
        float4 wB = *(const float4*)(Ws + k * 64 + c0 + 4);
        unsigned long long w0, w1, w2, w3;
        PACKF2(w0, wA.x, wA.y); PACKF2(w1, wA.z, wA.w);
        PACKF2(w2, wB.x, wB.y); PACKF2(w3, wB.z, wB.w);
        #pragma unroll
        for (int i = 0; i < 4; i++) {
            float a = As[(tr * 4 + i) * 64 + k];
            unsigned long long aa;
            PACKF2(aa, a, a);
            FMA2(acc[i][0], aa, w0);
            FMA2(acc[i][1], aa, w1);
            FMA2(acc[i][2], aa, w2);
            FMA2(acc[i][3], aa, w3);
        }
    }

    #pragma unroll
    for (int i = 0; i < 4; i++) {
        int node = nb0 + tr * 4 + i;
        if (node >= n) continue;
        float sc = do_scale ? g_dinv[node] : 1.0f;
        float y[8];
        #pragma unroll
        for (int p = 0; p < 4; p++) {
            float lo, hi;
            UNPACKF2(lo, hi, acc[i][p]);
            y[2 * p]     = sc * fmaxf(lo, 0.0f);
            y[2 * p + 1] = sc * fmaxf(hi, 0.0f);
        }
        unsigned r0, r1, r2, r3;
        PACK_BF16X2(r0, y[0], y[1]);
        PACK_BF16X2(r1, y[2], y[3]);
        PACK_BF16X2(r2, y[4], y[5]);
        PACK_BF16X2(r3, y[6], y[7]);
        *(uint4*)(Y + (size_t)node * 32 + c0 / 2) = make_uint4(r0, r1, r2, r3);
    }
}

// ---------------------------------------------------------------------------
// MLP head + log_softmax. One warp per FOUR nodes. Input g_a (bf16x2, relu'd).
// ---------------------------------------------------------------------------
__global__ void mlp_head_kernel(const float* __restrict__ Wp1,
                                const float* __restrict__ bp1,
                                const float* __restrict__ Wp2,
                                const float* __restrict__ bp2,
                                float* __restrict__ out, int n)
{
    __shared__ float W1s[64 * 32];
    __shared__ float W2s[32 * 40];
    __shared__ float b1s[32];
    __shared__ float b2s[40];

    int tid = threadIdx.x;
    for (int i = tid; i < 64 * 32; i += 256) W1s[i] = Wp1[i];
    for (int i = tid; i < 32 * 40; i += 256) W2s[i] = Wp2[i];
    if (tid < 32) b1s[tid] = bp1[tid];
    if (tid < 40) b2s[tid] = bp2[tid];
    __syncthreads();

    int warp = tid >> 5, lane = tid & 31;
    int node0 = (blockIdx.x * 8 + warp) * 4;
    if (node0 >= n) return;

    float2 xp[4];
    #pragma unroll
    for (int i = 0; i < 4; i++) {
        int nd = node0 + i;
        if (nd < n) {
            unsigned v = g_a[(size_t)nd * 32 + lane];
            xp[i] = make_float2(bf_lo(v), bf_hi(v));
        } else {
            xp[i] = make_float2(0.f, 0.f);
        }
    }

    float h[4];
    #pragma unroll
    for (int i = 0; i < 4; i++) h[i] = b1s[lane];
    #pragma unroll
    for (int k = 0; k < 32; k++) {
        float w0 = W1s[(2 * k    ) * 32 + lane];
        float w1 = W1s[(2 * k + 1) * 32 + lane];
        #pragma unroll
        for (int i = 0; i < 4; i++) {
            float xk0 = __shfl_sync(0xffffffffu, xp[i].x, k);
            float xk1 = __shfl_sync(0xffffffffu, xp[i].y, k);
            h[i] = fmaf(xk0, w0, h[i]);
            h[i] = fmaf(xk1, w1, h[i]);
        }
    }
    #pragma unroll
    for (int i = 0; i < 4; i++) h[i] = fmaxf(h[i], 0.0f);

    float o0[4], o1[4];
    #pragma unroll
    for (int i = 0; i < 4; i++) {
        o0[i] = b2s[lane];
        o1[i] = (lane < 8) ? b2s[32 + lane] : 0.0f;
    }
    #pragma unroll
    for (int j = 0; j < 32; j++) {
        float wa = W2s[j * 40 + lane];
        float wb = (lane < 8) ? W2s[j * 40 + 32 + lane] : 0.0f;
        #pragma unroll
        for (int i = 0; i < 4; i++) {
            float hj = __shfl_sync(0xffffffffu, h[i], j);
            o0[i] = fmaf(hj, wa, o0[i]);
            o1[i] = fmaf(hj, wb, o1[i]);
        }
    }

    #pragma unroll
    for (int i = 0; i < 4; i++) {
        int nd = node0 + i;
        if (nd >= n) break;
        float m = (lane < 8) ? fmaxf(o0[i], o1[i]) : o0[i];
        #pragma unroll
        for (int off = 16; off; off >>= 1)
            m = fmaxf(m, __shfl_xor_sync(0xffffffffu, m, off));

        float sum = expf(o0[i] - m) + ((lane < 8) ? expf(o1[i] - m) : 0.0f);
        #pragma unroll
        for (int off = 16; off; off >>= 1)
            sum += __shfl_xor_sync(0xffffffffu, sum, off);

        float lse = m + logf(sum);

        out[(size_t)nd * 40 + lane] = o0[i] - lse;
        if (lane < 8)
            out[(size_t)nd * 40 + 32 + lane] = o1[i] - lse;
    }
}

// ---------------------------------------------------------------------------
extern "C" void kernel_launch(void* const* d_in, const int* in_sizes, int n_in,
                              void* d_out, int out_size)
{
    const float* x   = (const float*)d_in[0];
    const int*   ei  = (const int*)  d_in[1];
    const float* W0  = (const float*)d_in[3];
    const float* b0  = (const float*)d_in[4];
    const float* W1  = (const float*)d_in[5];
    const float* b1  = (const float*)d_in[6];
    const float* W2  = (const float*)d_in[7];
    const float* b2  = (const float*)d_in[8];
    const float* Wp1 = (const float*)d_in[9];
    const float* bp1 = (const float*)d_in[10];
    const float* Wp2 = (const float*)d_in[11];
    const float* bp2 = (const float*)d_in[12];
    float* out = (float*)d_out;

    int n = in_sizes[0] / 64;
    int E = in_sizes[1] / 2;
    const int* src = ei;
    const int* dst = ei + E;

    int eb   = (E + 255) / 256;
    int wpn  = (n + 7) / 8;            // warp-per-node grid
    int hpn  = (n + 31) / 32;          // head: 4 nodes/warp
    int gem  = (n + 127) / 128;
    int nb2  = (n + SCAN_B - 1) / SCAN_B;
    int tot4 = n * 16;                 // float4 count for cvt
    int cv4  = (tot4 + 255) / 256;

    unsigned *pa, *pb, *px;
    cudaGetSymbolAddress((void**)&pa, g_a);
    cudaGetSymbolAddress((void**)&pb, g_b);
    cudaGetSymbolAddress((void**)&px, g_x16);

    // CSR build + pre-scaled input conversion (g_cnt re-zeroed in scan_local)
    count_kernel     <<<eb, 256>>>(dst, E);
    scan_local_kernel<<<nb2, SCAN_B>>>(n);
    scan_apply_kernel<<<nb2, SCAN_B>>>(n, E, nb2);
    fill_cvt_kernel  <<<eb + cv4, 256>>>(src, dst, x, E, eb, tot4);

    // Layer 0: x16 -> tmp -> a (scaled)
    agg_kernel <<<wpn, 256>>>(px, n);
    gemm_kernel<<<gem, 256>>>(pa, W0, b0, /*scale=*/1, n);
    // Layer 1: a -> tmp -> b (scaled)
    agg_kernel <<<wpn, 256>>>(pa, n);
    gemm_kernel<<<gem, 256>>>(pb, W1, b1, /*scale=*/1, n);
    // Layer 2: b -> tmp -> a (unscaled, feeds head)
    agg_kernel <<<wpn, 256>>>(pb, n);
    gemm_kernel<<<gem, 256>>>(pa, W2, b2, /*scale=*/0, n);

    // Head
    mlp_head_kernel<<<hpn, 256>>>(Wp1, bp1, Wp2, bp2, out, n);
}

// round 17
// speedup vs baseline: 1.5072x; 1.5072x over previous
#include <cuda_runtime.h>
#include <math.h>

#define NMAX 100000
#define EMAX 1600000
#define SCAN_B 1024
#define NBLK ((NMAX + SCAN_B - 1) / SCAN_B)   // 98

// Scratch (__device__ globals; no allocation allowed)
__device__ int      g_cnt[NMAX];           // zeroed statically; re-zeroed by scan_local
__device__ float    g_dinv[NMAX];
__device__ int      g_rowstart[NMAX + 1];
__device__ int      g_fill[NMAX];
__device__ int      g_bsum[NBLK + 1];
__device__ int2     g_csr[EMAX];           // packed (src, norm-as-int)  [R14 layout]
__device__ float    g_tmp[NMAX * 64];      // aggregation output (fp32, pre-GEMM)
__device__ unsigned g_x16[NMAX * 32];      // input features as bf16x2
__device__ unsigned g_a[NMAX * 32];        // activations as bf16x2 (ping)
__device__ unsigned g_b[NMAX * 32];        // activations as bf16x2 (pong)

// bf16 pack/unpack: unpack is ALU-pipe only (SHF/LOP3), no F2F.
#define PACK_BF16X2(r, lo, hi) \
    asm("cvt.rn.bf16x2.f32 %0, %1, %2;" : "=r"(r) : "f"(hi), "f"(lo))
__device__ __forceinline__ float bf_lo(unsigned u) { return __uint_as_float(u << 16); }
__device__ __forceinline__ float bf_hi(unsigned u) { return __uint_as_float(u & 0xffff0000u); }

// ---------------------------------------------------------------------------
__global__ void count_kernel(const int* __restrict__ dst, int E) {
    int i = blockIdx.x * blockDim.x + threadIdx.x;
    if (i < E) atomicAdd(&g_cnt[dst[i]], 1);
}

// ---------------------------------------------------------------------------
// scan_local: per-block scan of g_cnt, block totals to g_bsum.
// Also computes dinv and RE-ZEROES g_cnt for the next replay.
// ---------------------------------------------------------------------------
__global__ void scan_local_kernel(int n) {
    __shared__ int sm[SCAN_B];
    int t = threadIdx.x;
    int i = blockIdx.x * SCAN_B + t;
    int v = (i < n) ? g_cnt[i] : 0;
    if (i < n) {
        g_dinv[i] = rsqrtf((float)v + 1.0f);   // +1 self loop
        g_cnt[i] = 0;                          // ready for next replay
    }
    sm[t] = v;
    __syncthreads();
    #pragma unroll
    for (int off = 1; off < SCAN_B; off <<= 1) {
        int u = (t >= off) ? sm[t - off] : 0;
        __syncthreads();
        sm[t] += u;
        __syncthreads();
    }
    if (i < n) g_rowstart[i] = sm[t] - v;
    if (t == SCAN_B - 1) g_bsum[blockIdx.x] = sm[t];
}

// ---------------------------------------------------------------------------
// scan_apply: every block redundantly scans the 98 block sums in smem,
// then applies its offset. Replaces the separate bsums kernel.
// ---------------------------------------------------------------------------
__global__ void scan_apply_kernel(int n, int E, int nbsum) {
    __shared__ int sm[128];
    int t = threadIdx.x;
    if (t < 128) sm[t] = (t < nbsum) ? g_bsum[t] : 0;
    __syncthreads();
    #pragma unroll
    for (int off = 1; off < 128; off <<= 1) {
        int u = (t < 128 && t >= off) ? sm[t - off] : 0;
        __syncthreads();
        if (t < 128) sm[t] += u;
        __syncthreads();
    }
    int blkoff = (blockIdx.x == 0) ? 0 : sm[blockIdx.x - 1];  // exclusive
    int i = blockIdx.x * SCAN_B + t;
    if (i < n) {
        int r = g_rowstart[i] + blkoff;
        g_rowstart[i] = r;
        g_fill[i] = r;
    }
    if (i == 0) g_rowstart[n] = E;
}

// ---------------------------------------------------------------------------
// Fused fill + input conversion (block-range split). R14 semantics:
// fill: csr[pos] = (src, dinv[s]*dinv[d])   (8 B int2, norm embedded)
// cvt:  g_x16 = bf16x2(x)                    (unscaled)
// ---------------------------------------------------------------------------
__global__ void fill_cvt_kernel(const int* __restrict__ src,
                                const int* __restrict__ dst,
                                const float* __restrict__ x,
                                int E, int fillBlocks, int total4) {
    int b = blockIdx.x;
    int t = threadIdx.x;
    if (b < fillBlocks) {
        int e = b * 256 + t;
        if (e < E) {
            int s = src[e], d = dst[e];
            float nrm = g_dinv[s] * g_dinv[d];
            int pos = atomicAdd(&g_fill[d], 1);
            g_csr[pos] = make_int2(s, __float_as_int(nrm));
        }
    } else {
        int i = (b - fillBlocks) * 256 + t;
        if (i < total4) {
            float4 v = ((const float4*)x)[i];
            unsigned r0, r1;
            PACK_BF16X2(r0, v.x, v.y);
            PACK_BF16X2(r1, v.z, v.w);
            ((uint2*)g_x16)[i] = make_uint2(r0, r1);
        }
    }
}

// ---------------------------------------------------------------------------
// Aggregation (exact R14 structure): agg[i] = dinv_i^2 * x_i + sum_j nrm_ij x_j
// One warp per node; lane owns feature pair (2l,2l+1) as ONE bf16x2 word:
// neighbor row read = LDG.32 x 32 lanes = 128 B. Unrolled 4 edges/iter.
// ---------------------------------------------------------------------------
__global__ void agg_kernel(const unsigned* __restrict__ X, int n)
{
    int tid = threadIdx.x;
    int warp = tid >> 5, lane = tid & 31;
    int node = blockIdx.x * 8 + warp;
    if (node >= n) return;

    float di = g_dinv[node];
    unsigned sx = X[(size_t)node * 32 + lane];
    float ax = di * di * bf_lo(sx);
    float ay = di * di * bf_hi(sx);

    int beg = g_rowstart[node], end = g_rowstart[node + 1];
    int j = beg;
    for (; j + 3 < end; j += 4) {
        int2 e0 = g_csr[j];
        int2 e1 = g_csr[j + 1];
        int2 e2 = g_csr[j + 2];
        int2 e3 = g_csr[j + 3];
        unsigned v0 = X[(size_t)e0.x * 32 + lane];
        unsigned v1 = X[(size_t)e1.x * 32 + lane];
        unsigned v2 = X[(size_t)e2.x * 32 + lane];
        unsigned v3 = X[(size_t)e3.x * 32 + lane];
        float n0 = __int_as_float(e0.y);
        float n1 = __int_as_float(e1.y);
        float n2 = __int_as_float(e2.y);
        float n3 = __int_as_float(e3.y);
        ax = fmaf(n0, bf_lo(v0), ax); ay = fmaf(n0, bf_hi(v0), ay);
        ax = fmaf(n1, bf_lo(v1), ax); ay = fmaf(n1, bf_hi(v1), ay);
        ax = fmaf(n2, bf_lo(v2), ax); ay = fmaf(n2, bf_hi(v2), ay);
        ax = fmaf(n3, bf_lo(v3), ax); ay = fmaf(n3, bf_hi(v3), ay);
    }
    for (; j < end; j++) {
        int2 e = g_csr[j];
        unsigned v = X[(size_t)e.x * 32 + lane];
        float nm = __int_as_float(e.y);
        ax = fmaf(nm, bf_lo(v), ax);
        ay = fmaf(nm, bf_hi(v), ay);
    }

    ((float2*)g_tmp)[(size_t)node * 32 + lane] = make_float2(ax, ay);
}

// ---------------------------------------------------------------------------
// Tiled GEMM (exact R14): Y(bf16x2) = relu(g_tmp(fp32) @ W + b).
// Block: 256 thr, tile 128 nodes x 64. Thread tile 4x8, f32x2 packed FMAs.
// ---------------------------------------------------------------------------
#define PACKF2(out, lo, hi) \
    asm("mov.b64 %0, {%1, %2};" : "=l"(out) : "r"(__float_as_uint(lo)), "r"(__float_as_uint(hi)))
#define UNPACKF2(lo, hi, in) \
    do { unsigned _ulo, _uhi; \
         asm("mov.b64 {%0, %1}, %2;" : "=r"(_ulo), "=r"(_uhi) : "l"(in)); \
         lo = __uint_as_float(_ulo); hi = __uint_as_float(_uhi); } while (0)
#define FMA2(acc, a, b) \
    asm("fma.rn.f32x2 %0, %1, %2, %0;" : "+l"(acc) : "l"(a), "l"(b))

__global__ void gemm_kernel(unsigned* __restrict__ Y,
                            const float* __restrict__ W,
                            const float* __restrict__ bias, int n)
{
    __shared__ float As[128 * 64];   // 32 KB
    __shared__ float Ws[64 * 64];    // 16 KB

    int tid = threadIdx.x;
    #pragma unroll
    for (int i = tid; i < 4096; i += 256) Ws[i] = W[i];

    int nb0 = blockIdx.x * 128;
    {
        int arow = tid >> 1;
        int half = tid & 1;
        float4* dstp = (float4*)(As + arow * 64) + half * 8;
        if (nb0 + arow < n) {
            const float4* srcp = (const float4*)(g_tmp + (size_t)(nb0 + arow) * 64) + half * 8;
            #pragma unroll
            for (int q = 0; q < 8; q++) dstp[q] = srcp[q];
        } else {
            float4 z = make_float4(0.f, 0.f, 0.f, 0.f);
            #pragma unroll
            for (int q = 0; q < 8; q++) dstp[q] = z;
        }
    }
    __syncthreads();

    int tc = tid & 7;
    int tr = tid >> 3;
    int c0 = tc * 8;

    unsigned long long acc[4][4];
    {
        float4 bA = *(const float4*)(bias + c0);
        float4 bB = *(const float4*)(bias + c0 + 4);
        unsigned long long b0, b1, b2, b3;
        PACKF2(b0, bA.x, bA.y); PACKF2(b1, bA.z, bA.w);
        PACKF2(b2, bB.x, bB.y); PACKF2(b3, bB.z, bB.w);
        #pragma unroll
        for (int i = 0; i < 4; i++) {
            acc[i][0] = b0; acc[i][1] = b1; acc[i][2] = b2; acc[i][3] = b3;
        }
    }

    #pragma unroll 4
    for (int k = 0; k < 64; k++) {
        float4 wA = *(const float4*)(Ws + k * 64 + c0);
        float4 wB = *(const float4*)(Ws + k * 64 + c0 + 4);
        unsigned long long w0, w1, w2, w3;
        PACKF2(w0, wA.x, wA.y); PACKF2(w1, wA.z, wA.w);
        PACKF2(w2, wB.x, wB.y); PACKF2(w3, wB.z, wB.w);
        #pragma unroll
        for (int i = 0; i < 4; i++) {
            float a = As[(tr * 4 + i) * 64 + k];
            unsigned long long aa;
            PACKF2(aa, a, a);
            FMA2(acc[i][0], aa, w0);
            FMA2(acc[i][1], aa, w1);
            FMA2(acc[i][2], aa, w2);
            FMA2(acc[i][3], aa, w3);
        }
    }

    #pragma unroll
    for (int i = 0; i < 4; i++) {
        int node = nb0 + tr * 4 + i;
        if (node >= n) continue;
        float y[8];
        #pragma unroll
        for (int p = 0; p < 4; p++) {
            float lo, hi;
            UNPACKF2(lo, hi, acc[i][p]);
            y[2 * p]     = fmaxf(lo, 0.0f);
            y[2 * p + 1] = fmaxf(hi, 0.0f);
        }
        unsigned r0, r1, r2, r3;
        PACK_BF16X2(r0, y[0], y[1]);
        PACK_BF16X2(r1, y[2], y[3]);
        PACK_BF16X2(r2, y[4], y[5]);
        PACK_BF16X2(r3, y[6], y[7]);
        *(uint4*)(Y + (size_t)node * 32 + c0 / 2) = make_uint4(r0, r1, r2, r3);
    }
}

// ---------------------------------------------------------------------------
// MLP head + log_softmax (exact R14). One warp per FOUR nodes.
// ---------------------------------------------------------------------------
__global__ void mlp_head_kernel(const float* __restrict__ Wp1,
                                const float* __restrict__ bp1,
                                const float* __restrict__ Wp2,
                                const float* __restrict__ bp2,
                                float* __restrict__ out, int n)
{
    __shared__ float W1s[64 * 32];
    __shared__ float W2s[32 * 40];
    __shared__ float b1s[32];
    __shared__ float b2s[40];

    int tid = threadIdx.x;
    for (int i = tid; i < 64 * 32; i += 256) W1s[i] = Wp1[i];
    for (int i = tid; i < 32 * 40; i += 256) W2s[i] = Wp2[i];
    if (tid < 32) b1s[tid] = bp1[tid];
    if (tid < 40) b2s[tid] = bp2[tid];
    __syncthreads();

    int warp = tid >> 5, lane = tid & 31;
    int node0 = (blockIdx.x * 8 + warp) * 4;
    if (node0 >= n) return;

    float2 xp[4];
    #pragma unroll
    for (int i = 0; i < 4; i++) {
        int nd = node0 + i;
        if (nd < n) {
            unsigned v = g_a[(size_t)nd * 32 + lane];
            xp[i] = make_float2(bf_lo(v), bf_hi(v));
        } else {
            xp[i] = make_float2(0.f, 0.f);
        }
    }

    float h[4];
    #pragma unroll
    for (int i = 0; i < 4; i++) h[i] = b1s[lane];
    #pragma unroll
    for (int k = 0; k < 32; k++) {
        float w0 = W1s[(2 * k    ) * 32 + lane];
        float w1 = W1s[(2 * k + 1) * 32 + lane];
        #pragma unroll
        for (int i = 0; i < 4; i++) {
            float xk0 = __shfl_sync(0xffffffffu, xp[i].x, k);
            float xk1 = __shfl_sync(0xffffffffu, xp[i].y, k);
            h[i] = fmaf(xk0, w0, h[i]);
            h[i] = fmaf(xk1, w1, h[i]);
        }
    }
    #pragma unroll
    for (int i = 0; i < 4; i++) h[i] = fmaxf(h[i], 0.0f);

    float o0[4], o1[4];
    #pragma unroll
    for (int i = 0; i < 4; i++) {
        o0[i] = b2s[lane];
        o1[i] = (lane < 8) ? b2s[32 + lane] : 0.0f;
    }
    #pragma unroll
    for (int j = 0; j < 32; j++) {
        float wa = W2s[j * 40 + lane];
        float wb = (lane < 8) ? W2s[j * 40 + 32 + lane] : 0.0f;
        #pragma unroll
        for (int i = 0; i < 4; i++) {
            float hj = __shfl_sync(0xffffffffu, h[i], j);
            o0[i] = fmaf(hj, wa, o0[i]);
            o1[i] = fmaf(hj, wb, o1[i]);
        }
    }

    #pragma unroll
    for (int i = 0; i < 4; i++) {
        int nd = node0 + i;
        if (nd >= n) break;
        float m = (lane < 8) ? fmaxf(o0[i], o1[i]) : o0[i];
        #pragma unroll
        for (int off = 16; off; off >>= 1)
            m = fmaxf(m, __shfl_xor_sync(0xffffffffu, m, off));

        float sum = expf(o0[i] - m) + ((lane < 8) ? expf(o1[i] - m) : 0.0f);
        #pragma unroll
        for (int off = 16; off; off >>= 1)
            sum += __shfl_xor_sync(0xffffffffu, sum, off);

        float lse = m + logf(sum);

        out[(size_t)nd * 40 + lane] = o0[i] - lse;
        if (lane < 8)
            out[(size_t)nd * 40 + 32 + lane] = o1[i] - lse;
    }
}

// ---------------------------------------------------------------------------
extern "C" void kernel_launch(void* const* d_in, const int* in_sizes, int n_in,
                              void* d_out, int out_size)
{
    const float* x   = (const float*)d_in[0];
    const int*   ei  = (const int*)  d_in[1];
    const float* W0  = (const float*)d_in[3];
    const float* b0  = (const float*)d_in[4];
    const float* W1  = (const float*)d_in[5];
    const float* b1  = (const float*)d_in[6];
    const float* W2  = (const float*)d_in[7];
    const float* b2  = (const float*)d_in[8];
    const float* Wp1 = (const float*)d_in[9];
    const float* bp1 = (const float*)d_in[10];
    const float* Wp2 = (const float*)d_in[11];
    const float* bp2 = (const float*)d_in[12];
    float* out = (float*)d_out;

    int n = in_sizes[0] / 64;
    int E = in_sizes[1] / 2;
    const int* src = ei;
    const int* dst = ei + E;

    int eb   = (E + 255) / 256;
    int wpn  = (n + 7) / 8;            // warp-per-node grid
    int hpn  = (n + 31) / 32;          // head: 4 nodes/warp
    int gem  = (n + 127) / 128;
    int nb2  = (n + SCAN_B - 1) / SCAN_B;
    int tot4 = n * 16;                 // float4 count for cvt
    int cv4  = (tot4 + 255) / 256;

    unsigned *pa, *pb, *px;
    cudaGetSymbolAddress((void**)&pa, g_a);
    cudaGetSymbolAddress((void**)&pb, g_b);
    cudaGetSymbolAddress((void**)&px, g_x16);

    // CSR build + input conversion (g_cnt re-zeroed in scan_local)
    count_kernel     <<<eb, 256>>>(dst, E);
    scan_local_kernel<<<nb2, SCAN_B>>>(n);
    scan_apply_kernel<<<nb2, SCAN_B>>>(n, E, nb2);
    fill_cvt_kernel  <<<eb + cv4, 256>>>(src, dst, x, E, eb, tot4);

    // Layer 0: x16 -> tmp -> a
    agg_kernel <<<wpn, 256>>>(px, n);
    gemm_kernel<<<gem, 256>>>(pa, W0, b0, n);
    // Layer 1: a -> tmp -> b
    agg_kernel <<<wpn, 256>>>(pa, n);
    gemm_kernel<<<gem, 256>>>(pb, W1, b1, n);
    // Layer 2: b -> tmp -> a
    agg_kernel <<<wpn, 256>>>(pb, n);
    gemm_kernel<<<gem, 256>>>(pa, W2, b2, n);

    // Head
    mlp_head_kernel<<<hpn, 256>>>(Wp1, bp1, Wp2, bp2, out, n);
}